// round 1
// baseline (speedup 1.0000x reference)
#include <cuda_runtime.h>

#define NN 50000
#define NE 800000
#define ET 850000   // NE + NN self loops
#define D1 256      // heads(4) * h1(64)
#define D2 128

// ---------------- device scratch (static; no runtime allocation) ----------------
__device__ __align__(16) float g_xh1[NN * D1];   // X @ W1
__device__ __align__(16) float g_H1 [NN * D1];   // layer-1 output
__device__ __align__(16) float g_xh2[NN * D2];   // H1 @ W2
__device__ __align__(16) float g_as1[NN * 4];
__device__ __align__(16) float g_ad1[NN * 4];
__device__ float g_as2[NN];
__device__ float g_ad2[NN];
__device__ int g_deg[NN];
__device__ int g_rowptr[NN + 1];
__device__ int g_cursor[NN];
__device__ int g_eid[ET];
__device__ int g_bsum[64];

__device__ __forceinline__ int esrc(const int* __restrict__ ei, int e) {
    return e < NE ? ei[e] : e - NE;
}
__device__ __forceinline__ int edst(const int* __restrict__ ei, int e) {
    return e < NE ? ei[NE + e] : e - NE;
}
__device__ __forceinline__ float lrelu(float x) { return x > 0.f ? x : 0.2f * x; }

// ---------------- CSR build ----------------
__global__ void k_zero_deg() {
    int i = blockIdx.x * 256 + threadIdx.x;
    if (i < NN) g_deg[i] = 0;
}

__global__ void k_count(const int* __restrict__ ei) {
    int e = blockIdx.x * 256 + threadIdx.x;
    if (e < ET) atomicAdd(&g_deg[edst(ei, e)], 1);
}

__global__ void k_scan1() {
    __shared__ int s[1024];
    int t = threadIdx.x;
    int i = blockIdx.x * 1024 + t;
    int v = (i < NN) ? g_deg[i] : 0;
    s[t] = v;
    __syncthreads();
    #pragma unroll
    for (int off = 1; off < 1024; off <<= 1) {
        int x = (t >= off) ? s[t - off] : 0;
        __syncthreads();
        s[t] += x;
        __syncthreads();
    }
    if (i < NN) g_rowptr[i] = s[t] - v;   // exclusive
    if (t == 1023) g_bsum[blockIdx.x] = s[t];
}

__global__ void k_scan2(int nblocks) {
    if (threadIdx.x == 0) {
        int acc = 0;
        for (int b = 0; b < nblocks; b++) { int v = g_bsum[b]; g_bsum[b] = acc; acc += v; }
    }
}

__global__ void k_scan3() {
    int i = blockIdx.x * 1024 + threadIdx.x;
    if (i < NN) {
        int r = g_rowptr[i] + g_bsum[blockIdx.x];
        g_rowptr[i] = r;
        g_cursor[i] = r;
    }
    if (i == 0) g_rowptr[NN] = ET;
}

__global__ void k_fill(const int* __restrict__ ei) {
    int e = blockIdx.x * 256 + threadIdx.x;
    if (e < ET) {
        int d = edst(ei, e);
        int p = atomicAdd(&g_cursor[d], 1);
        g_eid[p] = e;
    }
}

// ---------------- SIMT SGEMM: C[M,N] = A[M,K] @ B[K,N]; N%64==0, K%16==0 ----------------
__global__ __launch_bounds__(256) void k_sgemm(const float* __restrict__ A,
                                               const float* __restrict__ B,
                                               float* __restrict__ C,
                                               int M, int N, int K) {
    __shared__ float As[16][68];   // padded stride (68*4B divisible by 16 -> float4 reads OK)
    __shared__ float Bs[16][64];
    int tid = threadIdx.x;
    int bm = blockIdx.y * 64, bn = blockIdx.x * 64;
    int tx = tid & 15, ty = tid >> 4;
    int arow = tid >> 2, acol = (tid & 3) * 4;
    int brow = tid >> 4, bcol = (tid & 15) * 4;

    float acc[4][4] = {};
    for (int k0 = 0; k0 < K; k0 += 16) {
        float4 av = make_float4(0.f, 0.f, 0.f, 0.f);
        if (bm + arow < M)
            av = *(const float4*)&A[(size_t)(bm + arow) * K + k0 + acol];
        As[acol + 0][arow] = av.x;
        As[acol + 1][arow] = av.y;
        As[acol + 2][arow] = av.z;
        As[acol + 3][arow] = av.w;
        float4 bv = *(const float4*)&B[(size_t)(k0 + brow) * N + bn + bcol];
        *(float4*)&Bs[brow][bcol] = bv;
        __syncthreads();
        #pragma unroll
        for (int k = 0; k < 16; k++) {
            float4 a = *(const float4*)&As[k][ty * 4];
            float4 b = *(const float4*)&Bs[k][tx * 4];
            acc[0][0] += a.x * b.x; acc[0][1] += a.x * b.y; acc[0][2] += a.x * b.z; acc[0][3] += a.x * b.w;
            acc[1][0] += a.y * b.x; acc[1][1] += a.y * b.y; acc[1][2] += a.y * b.z; acc[1][3] += a.y * b.w;
            acc[2][0] += a.z * b.x; acc[2][1] += a.z * b.y; acc[2][2] += a.z * b.z; acc[2][3] += a.z * b.w;
            acc[3][0] += a.w * b.x; acc[3][1] += a.w * b.y; acc[3][2] += a.w * b.z; acc[3][3] += a.w * b.w;
        }
        __syncthreads();
    }
    #pragma unroll
    for (int m = 0; m < 4; m++) {
        int r = bm + ty * 4 + m;
        if (r < M) {
            float4 v = make_float4(acc[m][0], acc[m][1], acc[m][2], acc[m][3]);
            *(float4*)&C[(size_t)r * N + bn + tx * 4] = v;
        }
    }
}

// ---------------- attention logit vectors ----------------
// layer1: a_src1[n,h] = sum_c xh1[n, h*64+c] * att_src1[h,c]   (warp per node, lane owns 8 channels)
__global__ __launch_bounds__(256) void k_attn1(const float* __restrict__ att_s,
                                               const float* __restrict__ att_d) {
    int w = (blockIdx.x * blockDim.x + threadIdx.x) >> 5;
    int lane = threadIdx.x & 31;
    if (w >= NN) return;
    const float4* xp = (const float4*)&g_xh1[(size_t)w * D1 + lane * 8];
    float4 x0 = xp[0], x1 = xp[1];
    const float4* ap = (const float4*)&att_s[lane * 8];
    float4 a0 = ap[0], a1 = ap[1];
    const float4* dp = (const float4*)&att_d[lane * 8];
    float4 d0 = dp[0], d1 = dp[1];
    float ss = x0.x*a0.x + x0.y*a0.y + x0.z*a0.z + x0.w*a0.w
             + x1.x*a1.x + x1.y*a1.y + x1.z*a1.z + x1.w*a1.w;
    float sd = x0.x*d0.x + x0.y*d0.y + x0.z*d0.z + x0.w*d0.w
             + x1.x*d1.x + x1.y*d1.y + x1.z*d1.z + x1.w*d1.w;
    #pragma unroll
    for (int m = 1; m < 8; m <<= 1) {
        ss += __shfl_xor_sync(0xffffffffu, ss, m);
        sd += __shfl_xor_sync(0xffffffffu, sd, m);
    }
    if ((lane & 7) == 0) {
        int h = lane >> 3;
        g_as1[w * 4 + h] = ss;
        g_ad1[w * 4 + h] = sd;
    }
}

// layer2: heads=1, C=128 (lane owns 4 channels)
__global__ __launch_bounds__(256) void k_attn2(const float* __restrict__ att_s,
                                               const float* __restrict__ att_d) {
    int w = (blockIdx.x * blockDim.x + threadIdx.x) >> 5;
    int lane = threadIdx.x & 31;
    if (w >= NN) return;
    float4 x = *(const float4*)&g_xh2[(size_t)w * D2 + lane * 4];
    float4 a = *(const float4*)&att_s[lane * 4];
    float4 d = *(const float4*)&att_d[lane * 4];
    float ss = x.x*a.x + x.y*a.y + x.z*a.z + x.w*a.w;
    float sd = x.x*d.x + x.y*d.y + x.z*d.z + x.w*d.w;
    #pragma unroll
    for (int m = 1; m < 32; m <<= 1) {
        ss += __shfl_xor_sync(0xffffffffu, ss, m);
        sd += __shfl_xor_sync(0xffffffffu, sd, m);
    }
    if (lane == 0) { g_as2[w] = ss; g_ad2[w] = sd; }
}

// ---------------- layer-1 aggregation: warp per destination node ----------------
__global__ __launch_bounds__(256) void k_agg1(const int* __restrict__ ei,
                                              const float* __restrict__ bias) {
    int w = (blockIdx.x * blockDim.x + threadIdx.x) >> 5;
    int lane = threadIdx.x & 31;
    if (w >= NN) return;
    int start = g_rowptr[w], end = g_rowptr[w + 1];
    float4 ad = *(const float4*)&g_ad1[w * 4];

    // pass A: softmax denominators per head (lane-parallel over edges)
    float s0 = 0.f, s1 = 0.f, s2 = 0.f, s3 = 0.f;
    for (int p = start + lane; p < end; p += 32) {
        int e = g_eid[p];
        int s = esrc(ei, e);
        float4 as = *(const float4*)&g_as1[s * 4];
        s0 += __expf(lrelu(as.x + ad.x));
        s1 += __expf(lrelu(as.y + ad.y));
        s2 += __expf(lrelu(as.z + ad.z));
        s3 += __expf(lrelu(as.w + ad.w));
    }
    #pragma unroll
    for (int m = 16; m >= 1; m >>= 1) {
        s0 += __shfl_xor_sync(0xffffffffu, s0, m);
        s1 += __shfl_xor_sync(0xffffffffu, s1, m);
        s2 += __shfl_xor_sync(0xffffffffu, s2, m);
        s3 += __shfl_xor_sync(0xffffffffu, s3, m);
    }

    // pass B: weighted feature gather (warp cooperates across 256 channels; lane owns 8)
    int head = lane >> 3;
    float adh = (head == 0) ? ad.x : (head == 1) ? ad.y : (head == 2) ? ad.z : ad.w;
    float den = (head == 0) ? s0 : (head == 1) ? s1 : (head == 2) ? s2 : s3;
    float inv = 1.0f / den;
    float acc0 = 0.f, acc1 = 0.f, acc2 = 0.f, acc3 = 0.f;
    float acc4 = 0.f, acc5 = 0.f, acc6 = 0.f, acc7 = 0.f;
    for (int p = start; p < end; ++p) {
        int e = g_eid[p];
        int s = esrc(ei, e);
        float wgt = __expf(lrelu(g_as1[s * 4 + head] + adh)) * inv;
        const float4* xp = (const float4*)&g_xh1[(size_t)s * D1 + lane * 8];
        float4 v0 = xp[0], v1 = xp[1];
        acc0 += wgt * v0.x; acc1 += wgt * v0.y; acc2 += wgt * v0.z; acc3 += wgt * v0.w;
        acc4 += wgt * v1.x; acc5 += wgt * v1.y; acc6 += wgt * v1.z; acc7 += wgt * v1.w;
    }
    const float4* bp = (const float4*)&bias[lane * 8];
    float4 b0 = bp[0], b1v = bp[1];
    float4* op = (float4*)&g_H1[(size_t)w * D1 + lane * 8];
    op[0] = make_float4(acc0 + b0.x, acc1 + b0.y, acc2 + b0.z, acc3 + b0.w);
    op[1] = make_float4(acc4 + b1v.x, acc5 + b1v.y, acc6 + b1v.z, acc7 + b1v.w);
}

// ---------------- layer-2 aggregation (heads=1, C=128) ----------------
__global__ __launch_bounds__(256) void k_agg2(const int* __restrict__ ei,
                                              const float* __restrict__ bias,
                                              float* __restrict__ out) {
    int w = (blockIdx.x * blockDim.x + threadIdx.x) >> 5;
    int lane = threadIdx.x & 31;
    if (w >= NN) return;
    int start = g_rowptr[w], end = g_rowptr[w + 1];
    float ad = g_ad2[w];

    float se = 0.f;
    for (int p = start + lane; p < end; p += 32) {
        int e = g_eid[p];
        int s = esrc(ei, e);
        se += __expf(lrelu(g_as2[s] + ad));
    }
    #pragma unroll
    for (int m = 16; m >= 1; m >>= 1)
        se += __shfl_xor_sync(0xffffffffu, se, m);
    float inv = 1.0f / se;

    float acc0 = 0.f, acc1 = 0.f, acc2 = 0.f, acc3 = 0.f;
    for (int p = start; p < end; ++p) {
        int e = g_eid[p];
        int s = esrc(ei, e);
        float wgt = __expf(lrelu(g_as2[s] + ad)) * inv;
        float4 v = *(const float4*)&g_xh2[(size_t)s * D2 + lane * 4];
        acc0 += wgt * v.x; acc1 += wgt * v.y; acc2 += wgt * v.z; acc3 += wgt * v.w;
    }
    float4 b = *(const float4*)&bias[lane * 4];
    *(float4*)&out[(size_t)w * D2 + lane * 4] =
        make_float4(acc0 + b.x, acc1 + b.y, acc2 + b.z, acc3 + b.w);
}

// ---------------- host launch ----------------
extern "C" void kernel_launch(void* const* d_in, const int* in_sizes, int n_in,
                              void* d_out, int out_size) {
    const float* X    = (const float*)d_in[0];
    const int*   ei   = (const int*)  d_in[1];
    const float* W1   = (const float*)d_in[2];
    const float* as1  = (const float*)d_in[3];
    const float* ad1  = (const float*)d_in[4];
    const float* b1   = (const float*)d_in[5];
    const float* W2   = (const float*)d_in[6];
    const float* as2  = (const float*)d_in[7];
    const float* ad2  = (const float*)d_in[8];
    const float* b2   = (const float*)d_in[9];
    float* out = (float*)d_out;

    float *p_xh1, *p_H1, *p_xh2;
    cudaGetSymbolAddress((void**)&p_xh1, g_xh1);
    cudaGetSymbolAddress((void**)&p_H1,  g_H1);
    cudaGetSymbolAddress((void**)&p_xh2, g_xh2);

    const int SCAN_BLOCKS = (NN + 1023) / 1024;   // 49
    const int NODE_BLOCKS = (NN + 7) / 8;         // warp-per-node, 8 warps/block

    // CSR by destination
    k_zero_deg<<<(NN + 255) / 256, 256>>>();
    k_count<<<(ET + 255) / 256, 256>>>(ei);
    k_scan1<<<SCAN_BLOCKS, 1024>>>();
    k_scan2<<<1, 32>>>(SCAN_BLOCKS);
    k_scan3<<<SCAN_BLOCKS, 1024>>>();
    k_fill<<<(ET + 255) / 256, 256>>>(ei);

    // layer 1
    k_sgemm<<<dim3(D1 / 64, (NN + 63) / 64), 256>>>(X, W1, p_xh1, NN, D1, 64);
    k_attn1<<<NODE_BLOCKS, 256>>>(as1, ad1);
    k_agg1<<<NODE_BLOCKS, 256>>>(ei, b1);

    // layer 2
    k_sgemm<<<dim3(D2 / 64, (NN + 63) / 64), 256>>>(p_H1, W2, p_xh2, NN, D2, D1);
    k_attn2<<<NODE_BLOCKS, 256>>>(as2, ad2);
    k_agg2<<<NODE_BLOCKS, 256>>>(ei, b2, out);
}

// round 3
// speedup vs baseline: 1.0771x; 1.0771x over previous
#include <cuda_runtime.h>
#include <cuda_bf16.h>
#include <cstdint>

#define NN 50000
#define NE 800000
#define ET 850000   // NE + NN self loops
#define D1 256      // heads(4) * h1(64)
#define D2 128

// ---------------- device scratch (static; no runtime allocation) ----------------
__device__ __align__(16) float g_xh1[NN * D1];   // X @ W1
__device__ __align__(16) float g_H1 [NN * D1];   // layer-1 output
__device__ __align__(16) float g_xh2[NN * D2];   // H1 @ W2
__device__ __align__(16) float g_as1[NN * 4];
__device__ __align__(16) float g_ad1[NN * 4];
__device__ float g_as2[NN];
__device__ float g_ad2[NN];
__device__ int g_deg[NN];
__device__ int g_rowptr[NN + 1];
__device__ int g_cursor[NN];
__device__ int g_eid[ET];
__device__ int g_bsum[64];
// transposed bf16 hi/lo weights: Wt[n][k]
__device__ __align__(16) __nv_bfloat16 g_wt1_hi[D1 * 64];
__device__ __align__(16) __nv_bfloat16 g_wt1_lo[D1 * 64];
__device__ __align__(16) __nv_bfloat16 g_wt2_hi[D2 * D1];
__device__ __align__(16) __nv_bfloat16 g_wt2_lo[D2 * D1];

__device__ __forceinline__ int esrc(const int* __restrict__ ei, int e) {
    return e < NE ? ei[e] : e - NE;
}
__device__ __forceinline__ int edst(const int* __restrict__ ei, int e) {
    return e < NE ? ei[NE + e] : e - NE;
}
__device__ __forceinline__ float lrelu(float x) { return x > 0.f ? x : 0.2f * x; }

// ---------------- CSR build ----------------
__global__ void k_zero_deg() {
    int i = blockIdx.x * 256 + threadIdx.x;
    if (i < NN) g_deg[i] = 0;
}

__global__ void k_count(const int* __restrict__ ei) {
    int e = blockIdx.x * 256 + threadIdx.x;
    if (e < ET) atomicAdd(&g_deg[edst(ei, e)], 1);
}

__global__ void k_scan1() {
    __shared__ int s[1024];
    int t = threadIdx.x;
    int i = blockIdx.x * 1024 + t;
    int v = (i < NN) ? g_deg[i] : 0;
    s[t] = v;
    __syncthreads();
    #pragma unroll
    for (int off = 1; off < 1024; off <<= 1) {
        int x = (t >= off) ? s[t - off] : 0;
        __syncthreads();
        s[t] += x;
        __syncthreads();
    }
    if (i < NN) g_rowptr[i] = s[t] - v;   // exclusive
    if (t == 1023) g_bsum[blockIdx.x] = s[t];
}

__global__ void k_scan2(int nblocks) {
    __shared__ int s[64];
    int t = threadIdx.x;
    int v = (t < nblocks) ? g_bsum[t] : 0;
    s[t] = v;
    __syncthreads();
    #pragma unroll
    for (int off = 1; off < 64; off <<= 1) {
        int x = (t >= off) ? s[t - off] : 0;
        __syncthreads();
        s[t] += x;
        __syncthreads();
    }
    if (t < nblocks) g_bsum[t] = s[t] - v;   // exclusive block offsets
}

__global__ void k_scan3() {
    int i = blockIdx.x * 1024 + threadIdx.x;
    if (i < NN) {
        int r = g_rowptr[i] + g_bsum[blockIdx.x];
        g_rowptr[i] = r;
        g_cursor[i] = r;
    }
    if (i == 0) g_rowptr[NN] = ET;
}

__global__ void k_fill(const int* __restrict__ ei) {
    int e = blockIdx.x * 256 + threadIdx.x;
    if (e < ET) {
        int d = edst(ei, e);
        int p = atomicAdd(&g_cursor[d], 1);
        g_eid[p] = e;
    }
}

// ---------------- weight transpose + bf16 hi/lo split ----------------
__global__ void k_prep_w1(const float* __restrict__ W1) {
    int idx = blockIdx.x * 256 + threadIdx.x;   // over 64*256
    if (idx >= 64 * D1) return;
    int k = idx / D1, n = idx % D1;
    float w = W1[idx];
    __nv_bfloat16 hi = __float2bfloat16(w);
    __nv_bfloat16 lo = __float2bfloat16(w - __bfloat162float(hi));
    g_wt1_hi[n * 64 + k] = hi;
    g_wt1_lo[n * 64 + k] = lo;
}
__global__ void k_prep_w2(const float* __restrict__ W2) {
    int idx = blockIdx.x * 256 + threadIdx.x;   // over 256*128
    if (idx >= D1 * D2) return;
    int k = idx / D2, n = idx % D2;
    float w = W2[idx];
    __nv_bfloat16 hi = __float2bfloat16(w);
    __nv_bfloat16 lo = __float2bfloat16(w - __bfloat162float(hi));
    g_wt2_hi[n * D1 + k] = hi;
    g_wt2_lo[n * D1 + k] = lo;
}

// ---------------- HMMA bf16 GEMM with 3-term compensation ----------------
// C[M, NCOL] = A[M, KTOT] @ Bt^T, Bt[n][k] bf16 hi/lo. Extended K' = 3*KTOT:
//   segment t=0: A_hi * B_hi ; t=1: A_lo * B_hi ; t=2: A_hi * B_lo
// Block tile 128x128, 8 warps (2x4) of 64x32, K-chunk 32, mma.m16n8k16.
#define KC 32
#define ASTR 40   // padded SMEM row stride in bf16 (80B, 16B-aligned, conflict-free)

template<int KTOT>
__global__ __launch_bounds__(256) void k_gemm_bf3(const float* __restrict__ A,
                                                  const __nv_bfloat16* __restrict__ BtHi,
                                                  const __nv_bfloat16* __restrict__ BtLo,
                                                  float* __restrict__ C,
                                                  int M, int NCOL) {
    __shared__ __nv_bfloat16 As[128 * ASTR];
    __shared__ __nv_bfloat16 Bs[128 * ASTR];

    int tid = threadIdx.x;
    int wid = tid >> 5, lane = tid & 31;
    int g = lane >> 2, tig = lane & 3;
    int wm = (wid >> 2) * 64;    // warp M offset in block
    int wn = (wid & 3) * 32;     // warp N offset in block
    int bm = blockIdx.y * 128;
    int bn = blockIdx.x * 128;

    float acc[4][4][4];
    #pragma unroll
    for (int mt = 0; mt < 4; mt++)
        #pragma unroll
        for (int nt = 0; nt < 4; nt++)
            #pragma unroll
            for (int f = 0; f < 4; f++) acc[mt][nt][f] = 0.f;

    // A fill indexing: 2 threads per row, 16 cols each
    int arow = tid >> 1;
    int acs = (tid & 1) * 16;

    for (int kc0 = 0; kc0 < 3 * KTOT; kc0 += KC) {
        int t = kc0 / KTOT;
        int kbase = kc0 % KTOT;

        // ---- fill A (fp32 -> bf16 hi or lo) ----
        {
            bool valid = (bm + arow) < M;
            const float* src = A + (size_t)(bm + arow) * KTOT + kbase + acs;
            #pragma unroll
            for (int j = 0; j < 4; j++) {
                float4 v = valid ? *(const float4*)(src + 4 * j)
                                 : make_float4(0.f, 0.f, 0.f, 0.f);
                uint32_t p0, p1;
                if (t == 1) {
                    __nv_bfloat16 hx = __float2bfloat16(v.x), hy = __float2bfloat16(v.y);
                    __nv_bfloat16 hz = __float2bfloat16(v.z), hw = __float2bfloat16(v.w);
                    __nv_bfloat16 lx = __float2bfloat16(v.x - __bfloat162float(hx));
                    __nv_bfloat16 ly = __float2bfloat16(v.y - __bfloat162float(hy));
                    __nv_bfloat16 lz = __float2bfloat16(v.z - __bfloat162float(hz));
                    __nv_bfloat16 lw = __float2bfloat16(v.w - __bfloat162float(hw));
                    p0 = (uint32_t)__bfloat16_as_ushort(lx) | ((uint32_t)__bfloat16_as_ushort(ly) << 16);
                    p1 = (uint32_t)__bfloat16_as_ushort(lz) | ((uint32_t)__bfloat16_as_ushort(lw) << 16);
                } else {
                    __nv_bfloat16 hx = __float2bfloat16(v.x), hy = __float2bfloat16(v.y);
                    __nv_bfloat16 hz = __float2bfloat16(v.z), hw = __float2bfloat16(v.w);
                    p0 = (uint32_t)__bfloat16_as_ushort(hx) | ((uint32_t)__bfloat16_as_ushort(hy) << 16);
                    p1 = (uint32_t)__bfloat16_as_ushort(hz) | ((uint32_t)__bfloat16_as_ushort(hw) << 16);
                }
                uint2 pk = make_uint2(p0, p1);
                *(uint2*)&As[arow * ASTR + acs + 4 * j] = pk;
            }
        }
        // ---- fill B (bf16 copy, choose hi/lo array) ----
        {
            const __nv_bfloat16* Bsrc = (t == 2) ? BtLo : BtHi;
            #pragma unroll
            for (int r = 0; r < 2; r++) {
                int idx = tid + r * 256;          // 512 x uint4
                int row = idx >> 2;
                int part = (idx & 3) * 8;         // bf16 col offset
                uint4 v = *(const uint4*)&Bsrc[(size_t)(bn + row) * KTOT + kbase + part];
                *(uint4*)&Bs[row * ASTR + part] = v;
            }
        }
        __syncthreads();

        // ---- mma over 2 k16 steps ----
        #pragma unroll
        for (int ks = 0; ks < KC; ks += 16) {
            uint32_t bfr[4][2];
            #pragma unroll
            for (int nt = 0; nt < 4; nt++) {
                int n = wn + nt * 8 + g;
                bfr[nt][0] = *(const uint32_t*)&Bs[n * ASTR + ks + 2 * tig];
                bfr[nt][1] = *(const uint32_t*)&Bs[n * ASTR + ks + 2 * tig + 8];
            }
            #pragma unroll
            for (int mt = 0; mt < 4; mt++) {
                int r0 = wm + mt * 16 + g;
                uint32_t a0 = *(const uint32_t*)&As[r0 * ASTR + ks + 2 * tig];
                uint32_t a1 = *(const uint32_t*)&As[(r0 + 8) * ASTR + ks + 2 * tig];
                uint32_t a2 = *(const uint32_t*)&As[r0 * ASTR + ks + 2 * tig + 8];
                uint32_t a3 = *(const uint32_t*)&As[(r0 + 8) * ASTR + ks + 2 * tig + 8];
                #pragma unroll
                for (int nt = 0; nt < 4; nt++) {
                    asm volatile(
                        "mma.sync.aligned.m16n8k16.row.col.f32.bf16.bf16.f32 "
                        "{%0,%1,%2,%3}, {%4,%5,%6,%7}, {%8,%9}, {%0,%1,%2,%3};"
                        : "+f"(acc[mt][nt][0]), "+f"(acc[mt][nt][1]),
                          "+f"(acc[mt][nt][2]), "+f"(acc[mt][nt][3])
                        : "r"(a0), "r"(a1), "r"(a2), "r"(a3),
                          "r"(bfr[nt][0]), "r"(bfr[nt][1]));
                }
            }
        }
        __syncthreads();
    }

    // ---- epilogue: direct fp32 stores (float2 per fragment half) ----
    #pragma unroll
    for (int mt = 0; mt < 4; mt++) {
        int r0 = bm + wm + mt * 16 + g;
        int r1 = r0 + 8;
        #pragma unroll
        for (int nt = 0; nt < 4; nt++) {
            int col = bn + wn + nt * 8 + 2 * tig;
            if (r0 < M)
                *(float2*)&C[(size_t)r0 * NCOL + col] = make_float2(acc[mt][nt][0], acc[mt][nt][1]);
            if (r1 < M)
                *(float2*)&C[(size_t)r1 * NCOL + col] = make_float2(acc[mt][nt][2], acc[mt][nt][3]);
        }
    }
}

// ---------------- attention logit vectors ----------------
__global__ __launch_bounds__(256) void k_attn1(const float* __restrict__ att_s,
                                               const float* __restrict__ att_d) {
    int w = (blockIdx.x * blockDim.x + threadIdx.x) >> 5;
    int lane = threadIdx.x & 31;
    if (w >= NN) return;
    const float4* xp = (const float4*)&g_xh1[(size_t)w * D1 + lane * 8];
    float4 x0 = xp[0], x1 = xp[1];
    const float4* ap = (const float4*)&att_s[lane * 8];
    float4 a0 = ap[0], a1 = ap[1];
    const float4* dp = (const float4*)&att_d[lane * 8];
    float4 d0 = dp[0], d1 = dp[1];
    float ss = x0.x*a0.x + x0.y*a0.y + x0.z*a0.z + x0.w*a0.w
             + x1.x*a1.x + x1.y*a1.y + x1.z*a1.z + x1.w*a1.w;
    float sd = x0.x*d0.x + x0.y*d0.y + x0.z*d0.z + x0.w*d0.w
             + x1.x*d1.x + x1.y*d1.y + x1.z*d1.z + x1.w*d1.w;
    #pragma unroll
    for (int m = 1; m < 8; m <<= 1) {
        ss += __shfl_xor_sync(0xffffffffu, ss, m);
        sd += __shfl_xor_sync(0xffffffffu, sd, m);
    }
    if ((lane & 7) == 0) {
        int h = lane >> 3;
        g_as1[w * 4 + h] = ss;
        g_ad1[w * 4 + h] = sd;
    }
}

__global__ __launch_bounds__(256) void k_attn2(const float* __restrict__ att_s,
                                               const float* __restrict__ att_d) {
    int w = (blockIdx.x * blockDim.x + threadIdx.x) >> 5;
    int lane = threadIdx.x & 31;
    if (w >= NN) return;
    float4 x = *(const float4*)&g_xh2[(size_t)w * D2 + lane * 4];
    float4 a = *(const float4*)&att_s[lane * 4];
    float4 d = *(const float4*)&att_d[lane * 4];
    float ss = x.x*a.x + x.y*a.y + x.z*a.z + x.w*a.w;
    float sd = x.x*d.x + x.y*d.y + x.z*d.z + x.w*d.w;
    #pragma unroll
    for (int m = 1; m < 32; m <<= 1) {
        ss += __shfl_xor_sync(0xffffffffu, ss, m);
        sd += __shfl_xor_sync(0xffffffffu, sd, m);
    }
    if (lane == 0) { g_as2[w] = ss; g_ad2[w] = sd; }
}

// ---------------- layer-1 aggregation: warp per destination node ----------------
__global__ __launch_bounds__(256) void k_agg1(const int* __restrict__ ei,
                                              const float* __restrict__ bias) {
    int w = (blockIdx.x * blockDim.x + threadIdx.x) >> 5;
    int lane = threadIdx.x & 31;
    if (w >= NN) return;
    int start = g_rowptr[w], end = g_rowptr[w + 1];
    float4 ad = *(const float4*)&g_ad1[w * 4];

    float s0 = 0.f, s1 = 0.f, s2 = 0.f, s3 = 0.f;
    for (int p = start + lane; p < end; p += 32) {
        int e = g_eid[p];
        int s = esrc(ei, e);
        float4 as = *(const float4*)&g_as1[s * 4];
        s0 += __expf(lrelu(as.x + ad.x));
        s1 += __expf(lrelu(as.y + ad.y));
        s2 += __expf(lrelu(as.z + ad.z));
        s3 += __expf(lrelu(as.w + ad.w));
    }
    #pragma unroll
    for (int m = 16; m >= 1; m >>= 1) {
        s0 += __shfl_xor_sync(0xffffffffu, s0, m);
        s1 += __shfl_xor_sync(0xffffffffu, s1, m);
        s2 += __shfl_xor_sync(0xffffffffu, s2, m);
        s3 += __shfl_xor_sync(0xffffffffu, s3, m);
    }

    int head = lane >> 3;
    float adh = (head == 0) ? ad.x : (head == 1) ? ad.y : (head == 2) ? ad.z : ad.w;
    float den = (head == 0) ? s0 : (head == 1) ? s1 : (head == 2) ? s2 : s3;
    float inv = 1.0f / den;
    float acc0 = 0.f, acc1 = 0.f, acc2 = 0.f, acc3 = 0.f;
    float acc4 = 0.f, acc5 = 0.f, acc6 = 0.f, acc7 = 0.f;
    for (int p = start; p < end; ++p) {
        int e = g_eid[p];
        int s = esrc(ei, e);
        float wgt = __expf(lrelu(g_as1[s * 4 + head] + adh)) * inv;
        const float4* xp = (const float4*)&g_xh1[(size_t)s * D1 + lane * 8];
        float4 v0 = xp[0], v1 = xp[1];
        acc0 += wgt * v0.x; acc1 += wgt * v0.y; acc2 += wgt * v0.z; acc3 += wgt * v0.w;
        acc4 += wgt * v1.x; acc5 += wgt * v1.y; acc6 += wgt * v1.z; acc7 += wgt * v1.w;
    }
    const float4* bp = (const float4*)&bias[lane * 8];
    float4 b0 = bp[0], b1v = bp[1];
    float4* op = (float4*)&g_H1[(size_t)w * D1 + lane * 8];
    op[0] = make_float4(acc0 + b0.x, acc1 + b0.y, acc2 + b0.z, acc3 + b0.w);
    op[1] = make_float4(acc4 + b1v.x, acc5 + b1v.y, acc6 + b1v.z, acc7 + b1v.w);
}

// ---------------- layer-2 aggregation (heads=1, C=128) ----------------
__global__ __launch_bounds__(256) void k_agg2(const int* __restrict__ ei,
                                              const float* __restrict__ bias,
                                              float* __restrict__ out) {
    int w = (blockIdx.x * blockDim.x + threadIdx.x) >> 5;
    int lane = threadIdx.x & 31;
    if (w >= NN) return;
    int start = g_rowptr[w], end = g_rowptr[w + 1];
    float ad = g_ad2[w];

    float se = 0.f;
    for (int p = start + lane; p < end; p += 32) {
        int e = g_eid[p];
        int s = esrc(ei, e);
        se += __expf(lrelu(g_as2[s] + ad));
    }
    #pragma unroll
    for (int m = 16; m >= 1; m >>= 1)
        se += __shfl_xor_sync(0xffffffffu, se, m);
    float inv = 1.0f / se;

    float acc0 = 0.f, acc1 = 0.f, acc2 = 0.f, acc3 = 0.f;
    for (int p = start; p < end; ++p) {
        int e = g_eid[p];
        int s = esrc(ei, e);
        float wgt = __expf(lrelu(g_as2[s] + ad)) * inv;
        float4 v = *(const float4*)&g_xh2[(size_t)s * D2 + lane * 4];
        acc0 += wgt * v.x; acc1 += wgt * v.y; acc2 += wgt * v.z; acc3 += wgt * v.w;
    }
    float4 b = *(const float4*)&bias[lane * 4];
    *(float4*)&out[(size_t)w * D2 + lane * 4] =
        make_float4(acc0 + b.x, acc1 + b.y, acc2 + b.z, acc3 + b.w);
}

// ---------------- host launch ----------------
extern "C" void kernel_launch(void* const* d_in, const int* in_sizes, int n_in,
                              void* d_out, int out_size) {
    const float* X    = (const float*)d_in[0];
    const int*   ei   = (const int*)  d_in[1];
    const float* W1   = (const float*)d_in[2];
    const float* as1  = (const float*)d_in[3];
    const float* ad1  = (const float*)d_in[4];
    const float* b1   = (const float*)d_in[5];
    const float* W2   = (const float*)d_in[6];
    const float* as2  = (const float*)d_in[7];
    const float* ad2  = (const float*)d_in[8];
    const float* b2   = (const float*)d_in[9];
    float* out = (float*)d_out;

    float *p_xh1, *p_H1, *p_xh2;
    cudaGetSymbolAddress((void**)&p_xh1, g_xh1);
    cudaGetSymbolAddress((void**)&p_H1,  g_H1);
    cudaGetSymbolAddress((void**)&p_xh2, g_xh2);
    __nv_bfloat16 *p_w1h, *p_w1l, *p_w2h, *p_w2l;
    cudaGetSymbolAddress((void**)&p_w1h, g_wt1_hi);
    cudaGetSymbolAddress((void**)&p_w1l, g_wt1_lo);
    cudaGetSymbolAddress((void**)&p_w2h, g_wt2_hi);
    cudaGetSymbolAddress((void**)&p_w2l, g_wt2_lo);

    const int SCAN_BLOCKS = (NN + 1023) / 1024;   // 49
    const int NODE_BLOCKS = (NN + 7) / 8;
    const int M_BLOCKS = (NN + 127) / 128;        // 391

    // CSR by destination
    k_zero_deg<<<(NN + 255) / 256, 256>>>();
    k_count<<<(ET + 255) / 256, 256>>>(ei);
    k_scan1<<<SCAN_BLOCKS, 1024>>>();
    k_scan2<<<1, 64>>>(SCAN_BLOCKS);
    k_scan3<<<SCAN_BLOCKS, 1024>>>();
    k_fill<<<(ET + 255) / 256, 256>>>(ei);

    // weight prep (tiny)
    k_prep_w1<<<(64 * D1 + 255) / 256, 256>>>(W1);
    k_prep_w2<<<(D1 * D2 + 255) / 256, 256>>>(W2);

    // layer 1
    k_gemm_bf3<64><<<dim3(D1 / 128, M_BLOCKS), 256>>>(X, p_w1h, p_w1l, p_xh1, NN, D1);
    k_attn1<<<NODE_BLOCKS, 256>>>(as1, ad1);
    k_agg1<<<NODE_BLOCKS, 256>>>(ei, b1);

    // layer 2
    k_gemm_bf3<D1><<<dim3(D2 / 128, M_BLOCKS), 256>>>(p_H1, p_w2h, p_w2l, p_xh2, NN, D2);
    k_attn2<<<NODE_BLOCKS, 256>>>(as2, ad2);
    k_agg2<<<NODE_BLOCKS, 256>>>(ei, b2, out);
}